// round 2
// baseline (speedup 1.0000x reference)
#include <cuda_runtime.h>

// Problem constants
#define NV   16384          // number of vectors (16*32*32)
#define KC   8192           // codebook size (reference's NUM_TOKENS)
#define DIMV 256
#define HWSZ 1024           // 32*32 per batch image
#define BDHW (DIMV*HWSZ)    // stride of one batch image in z (262144)

#define DECAYF 0.99f
#define OMDF   0.01f        // float(1.0 - 0.99)
#define EPSF   1e-5f
#define BETAD  0.25

// Output layout (float32, concatenated in reference return order)
#define OUT_OFF  0
#define LOSS_OFF 4194304
#define IDX_OFF  4194305
#define CS_OFF   4210689
#define EMAW_OFF 4218881
#define EMB_OFF  6316033

// Scratch (no allocations allowed -> __device__ globals)
__device__ unsigned long long g_argmin[NV];
__device__ float  g_enorm[KC];
__device__ float  g_esum[KC * DIMV];
__device__ float  g_counts[KC];
__device__ double g_loss;
__device__ float  g_ncs[KC];

// ---------------------------------------------------------------------------
// K0: zero/initialize scratch (graph replays -> must re-init every launch)
// ---------------------------------------------------------------------------
__global__ void k_zero() {
    int i = blockIdx.x * blockDim.x + threadIdx.x;
    int stride = gridDim.x * blockDim.x;
    for (int j = i; j < KC * DIMV; j += stride) g_esum[j] = 0.f;
    for (int j = i; j < NV; j += stride) g_argmin[j] = 0xFFFFFFFFFFFFFFFFull;
    for (int j = i; j < KC; j += stride) g_counts[j] = 0.f;
    if (i == 0) g_loss = 0.0;
}

// ---------------------------------------------------------------------------
// K0b: ||e_k||^2 per codebook row (warp per row)
// ---------------------------------------------------------------------------
__global__ void k_enorm(const float* __restrict__ e) {
    int warp = (blockIdx.x * blockDim.x + threadIdx.x) >> 5;
    int lane = threadIdx.x & 31;
    if (warp >= KC) return;
    const float* row = e + warp * DIMV;
    float s = 0.f;
    #pragma unroll
    for (int d = lane; d < DIMV; d += 32) { float v = row[d]; s += v * v; }
    #pragma unroll
    for (int o = 16; o; o >>= 1) s += __shfl_xor_sync(0xFFFFFFFFu, s, o);
    if (lane == 0) g_enorm[warp] = s;
}

// ---------------------------------------------------------------------------
// K1: tiled fp32 GEMM (tokens x codes over K=256) with fused argmin.
// Block tile: 128 tokens x 128 codes, K-chunks of 8. 256 threads, 8x8/thread.
// Distance surrogate: s = ||e||^2 - 2 z.e (adding ||z||^2 doesn't change argmin).
// Packed (orderable-float-bits << 32 | code) + atomicMin -> global argmin,
// ties resolve to smallest code index, matching jnp.argmin.
// ---------------------------------------------------------------------------
__global__ void __launch_bounds__(256, 2)
k_dist(const float* __restrict__ z, const float* __restrict__ e) {
    __shared__ float Zs[8][132];
    __shared__ float Es[8][132];
    __shared__ float En[128];

    int tid = threadIdx.x;
    int kc0 = blockIdx.x * 128;   // code tile
    int n0  = blockIdx.y * 128;   // token tile (stays within one batch image)
    int b   = n0 >> 10;
    int hw  = n0 & 1023;
    const float* zb = z + (long)b * BDHW + hw;   // element (d, t): zb[d*1024 + t]

    if (tid < 128) En[tid] = g_enorm[kc0 + tid];

    float acc[8][8];
    #pragma unroll
    for (int i = 0; i < 8; i++)
        #pragma unroll
        for (int j = 0; j < 8; j++) acc[i][j] = 0.f;

    int tx = tid & 15;   // code group
    int ty = tid >> 4;   // token group

    for (int k0 = 0; k0 < DIMV; k0 += 8) {
        __syncthreads();
        // Load Z tile: [kk][tm], coalesced over tm
        {
            int tm  = tid & 127;
            int kkb = tid >> 7;
            #pragma unroll
            for (int it = 0; it < 4; it++) {
                int kk = kkb + it * 2;
                Zs[kk][tm] = zb[(k0 + kk) * HWSZ + tm];
            }
        }
        // Load E tile: [kk][tn], kk is the contiguous (d) axis in gmem
        {
            int kk  = tid & 7;
            int tnb = tid >> 3;
            #pragma unroll
            for (int it = 0; it < 4; it++) {
                int tn = tnb + it * 32;
                Es[kk][tn] = e[(long)(kc0 + tn) * DIMV + k0 + kk];
            }
        }
        __syncthreads();
        #pragma unroll
        for (int kk = 0; kk < 8; kk++) {
            float av[8], bv[8];
            float4 a0 = *(const float4*)&Zs[kk][ty * 8];
            float4 a1 = *(const float4*)&Zs[kk][ty * 8 + 4];
            float4 b0 = *(const float4*)&Es[kk][tx * 8];
            float4 b1 = *(const float4*)&Es[kk][tx * 8 + 4];
            av[0]=a0.x; av[1]=a0.y; av[2]=a0.z; av[3]=a0.w;
            av[4]=a1.x; av[5]=a1.y; av[6]=a1.z; av[7]=a1.w;
            bv[0]=b0.x; bv[1]=b0.y; bv[2]=b0.z; bv[3]=b0.w;
            bv[4]=b1.x; bv[5]=b1.y; bv[6]=b1.z; bv[7]=b1.w;
            #pragma unroll
            for (int i = 0; i < 8; i++)
                #pragma unroll
                for (int j = 0; j < 8; j++)
                    acc[i][j] += av[i] * bv[j];
        }
    }

    // Fused argmin over this block's 128 codes
    #pragma unroll
    for (int i = 0; i < 8; i++) {
        unsigned long long best = 0xFFFFFFFFFFFFFFFFull;
        #pragma unroll
        for (int j = 0; j < 8; j++) {
            int code = kc0 + tx * 8 + j;
            float s = En[tx * 8 + j] - 2.f * acc[i][j];
            unsigned int bits = __float_as_uint(s);
            unsigned int key = (bits & 0x80000000u) ? ~bits : (bits | 0x80000000u);
            unsigned long long p = ((unsigned long long)key << 32) | (unsigned int)code;
            best = min(best, p);
        }
        // reduce across the 16 tx lanes sharing this token (lane groups of 16)
        #pragma unroll
        for (int o = 8; o; o >>= 1) {
            unsigned long long other = __shfl_xor_sync(0xFFFFFFFFu, best, o);
            best = min(best, other);
        }
        if (tx == 0)
            atomicMin(&g_argmin[n0 + ty * 8 + i], best);
    }
}

// ---------------------------------------------------------------------------
// K2: per-token gather/scatter. 128 tokens per block (one thread each).
//  - writes out[b,d,h,w] = zp + (e[idx,d] - zp)   (straight-through, fp32 exact)
//  - idx -> output (as float)
//  - counts / embed_sum segment sums via atomics
//  - loss partial sums -> double atomic
// z reads / out writes coalesced over threads; e rows stream through L1.
// ---------------------------------------------------------------------------
__global__ void __launch_bounds__(128)
k_scatter(const float* __restrict__ z, const float* __restrict__ e,
          float* __restrict__ out) {
    int t = threadIdx.x;
    int n = blockIdx.x * 128 + t;
    int idx = (int)(g_argmin[n] & 0xFFFFFFFFu);
    out[IDX_OFF + n] = (float)idx;
    atomicAdd(&g_counts[idx], 1.f);

    int b = n >> 10, hw = n & 1023;
    const float* zb = z + (long)b * BDHW + hw;
    float*       ob = out + OUT_OFF + (long)b * BDHW + hw;
    const float* er = e + (long)idx * DIMV;
    float* es = g_esum + (long)idx * DIMV;

    float lacc = 0.f;
    #pragma unroll 4
    for (int d = 0; d < DIMV; d++) {
        float zv = zb[d * HWSZ];
        float ev = er[d];
        float diff = ev - zv;       // (z_q - zp) rounded, like the reference STE
        lacc += diff * diff;
        ob[d * HWSZ] = zv + diff;
        atomicAdd(&es[d], zv);
    }

    __shared__ float red[128];
    red[t] = lacc;
    __syncthreads();
    #pragma unroll
    for (int s = 64; s; s >>= 1) {
        if (t < s) red[t] += red[t + s];
        __syncthreads();
    }
    if (t == 0) atomicAdd(&g_loss, (double)red[0]);
}

// ---------------------------------------------------------------------------
// K3: cluster-size EMA + normalization denominator (single block), + loss out
// ---------------------------------------------------------------------------
__global__ void __launch_bounds__(1024)
k_cs(const float* __restrict__ cluster_size, float* __restrict__ out) {
    __shared__ float red[1024];
    int t = threadIdx.x;
    float csl[8];
    float local = 0.f;
    #pragma unroll
    for (int r = 0; r < 8; r++) {
        int k = t * 8 + r;
        float cs = cluster_size[k] * DECAYF + OMDF * g_counts[k] + EPSF;
        csl[r] = cs;
        local += cs;
    }
    red[t] = local;
    __syncthreads();
    #pragma unroll
    for (int s = 512; s; s >>= 1) {
        if (t < s) red[t] += red[t + s];
        __syncthreads();
    }
    float denom = red[0] + (float)(KC * 1e-05);   // sum(cs) + NUM_TOKENS*EPS
    #pragma unroll
    for (int r = 0; r < 8; r++) {
        int k = t * 8 + r;
        float v = csl[r] / denom;
        g_ncs[k] = v;
        out[CS_OFF + k] = v;
    }
    if (t == 0)
        out[LOSS_OFF] = (float)(BETAD * g_loss / (double)(NV * DIMV));
}

// ---------------------------------------------------------------------------
// K4: new_ema_w and new_embedding
// ---------------------------------------------------------------------------
__global__ void k_final(const float* __restrict__ ema_w, float* __restrict__ out) {
    int i = blockIdx.x * blockDim.x + threadIdx.x;
    if (i >= KC * DIMV) return;
    int k = i >> 8;
    float v = ema_w[i] * DECAYF + OMDF * g_esum[i];
    out[EMAW_OFF + i] = v;
    out[EMB_OFF + i]  = v / g_ncs[k];
}

// ---------------------------------------------------------------------------
extern "C" void kernel_launch(void* const* d_in, const int* in_sizes, int n_in,
                              void* d_out, int out_size) {
    (void)in_sizes; (void)n_in; (void)out_size;
    const float* z            = (const float*)d_in[0];  // [16,256,32,32]
    const float* embedding    = (const float*)d_in[1];  // [8192,256]
    const float* cluster_size = (const float*)d_in[2];  // [8192]
    const float* ema_w        = (const float*)d_in[3];  // [8192,256]
    float* out = (float*)d_out;

    k_zero<<<4096, 512>>>();
    k_enorm<<<1024, 256>>>(embedding);
    {
        dim3 grid(KC / 128, NV / 128);   // (64 code tiles, 128 token tiles)
        k_dist<<<grid, 256>>>(z, embedding);
    }
    k_scatter<<<NV / 128, 128>>>(z, embedding, out);
    k_cs<<<1, 1024>>>(cluster_size, out);
    k_final<<<(KC * DIMV) / 256, 256>>>(ema_w, out);
}

// round 4
// speedup vs baseline: 3.1334x; 3.1334x over previous
#include <cuda_runtime.h>
#include <cuda_bf16.h>
#include <cstdint>

// ---------------- problem constants ----------------
#define NV   16384
#define KC   8192
#define DIMV 256
#define HWSZ 1024
#define BDHW (DIMV*HWSZ)

#define DECAYF 0.99f
#define OMDF   0.01f
#define EPSF   1e-5f
#define TCAND  1.5f     // candidate threshold (>=14 sigma of bf16 1-pass error)

// output layout (float32, concatenated)
#define OUT_OFF  0
#define LOSS_OFF 4194304
#define IDX_OFF  4194305
#define CS_OFF   4210689
#define EMAW_OFF 4218881
#define EMB_OFF  6316033

// ---------------- scratch ----------------
__device__ __nv_bfloat16 g_zh[NV * DIMV];   // token-major bf16 z
__device__ __nv_bfloat16 g_eh[KC * DIMV];   // bf16 codebook
__device__ float  g_enorm[KC];
__device__ int    g_idx[NV];
__device__ float  g_esum[KC * DIMV];
__device__ float  g_counts[KC];
__device__ double g_loss;
__device__ float  g_ncs[KC];
__device__ int    g_nflag;
__device__ int    g_flaglist[NV];

// ---------------- helpers ----------------
__device__ __forceinline__ uint32_t smem_u32(const void* p) {
    uint32_t a;
    asm("{ .reg .u64 t; cvta.to.shared.u64 t, %1; cvt.u32.u64 %0, t; }" : "=r"(a) : "l"(p));
    return a;
}
#define CP_ASYNC16(sm, gp) asm volatile("cp.async.cg.shared.global [%0], [%1], 16;" :: "r"(sm), "l"(gp) : "memory")
#define CP_COMMIT() asm volatile("cp.async.commit_group;" ::: "memory")
#define CP_WAIT1()  asm volatile("cp.async.wait_group 1;" ::: "memory")

__device__ __forceinline__ void ldsm4(uint32_t& r0, uint32_t& r1, uint32_t& r2, uint32_t& r3, uint32_t a) {
    asm volatile("ldmatrix.sync.aligned.m8n8.x4.shared.b16 {%0,%1,%2,%3}, [%4];"
                 : "=r"(r0), "=r"(r1), "=r"(r2), "=r"(r3) : "r"(a));
}
__device__ __forceinline__ void mma16816(float& c0, float& c1, float& c2, float& c3,
                                         uint32_t a0, uint32_t a1, uint32_t a2, uint32_t a3,
                                         uint32_t b0, uint32_t b1) {
    asm volatile("mma.sync.aligned.m16n8k16.row.col.f32.bf16.bf16.f32 "
                 "{%0,%1,%2,%3}, {%4,%5,%6,%7}, {%8,%9}, {%0,%1,%2,%3};"
                 : "+f"(c0), "+f"(c1), "+f"(c2), "+f"(c3)
                 : "r"(a0), "r"(a1), "r"(a2), "r"(a3), "r"(b0), "r"(b1));
}
__device__ __forceinline__ uint32_t fkey(float s) {
    uint32_t b = __float_as_uint(s);
    return (b & 0x80000000u) ? ~b : (b | 0x80000000u);
}
__device__ __forceinline__ float funkey(uint32_t k) {
    return (k & 0x80000000u) ? __uint_as_float(k ^ 0x80000000u) : __uint_as_float(~k);
}

// smem layout of k_dist (relative to 1024-aligned base)
#define NT     64                 // codes per tile
#define TILES  (KC / NT)          // 128
#define SA     0                  // A: 128 x 512B = 65536
#define SB     65536              // B: 2 x 32768
#define SCNT   (SB + 65536)       // 128 x 4
#define SMK    (SCNT + 512)       // 128 x 4
#define SCODE  (SMK + 512)        // 128 x 32 x 4
#define SS     (SCODE + 16384)    // 128 x 32 x 4
#define SM_SZ  (SS + 16384 + 1024)

// ---------------------------------------------------------------------------
// P1: z [16,256,32,32] -> token-major bf16 (32x32 transpose tiles)
// ---------------------------------------------------------------------------
__global__ void p_zsplit(const float* __restrict__ z) {
    __shared__ float tile[32][33];
    int b = blockIdx.z, d0 = blockIdx.y * 32, hw0 = blockIdx.x * 32;
    int tx = threadIdx.x, ty = threadIdx.y;
    #pragma unroll
    for (int k = 0; k < 4; k++) {
        int d = d0 + ty + k * 8;
        tile[ty + k * 8][tx] = z[b * BDHW + d * HWSZ + hw0 + tx];
    }
    __syncthreads();
    #pragma unroll
    for (int k = 0; k < 4; k++) {
        int hw = hw0 + ty + k * 8;
        int n = b * HWSZ + hw;
        g_zh[n * DIMV + d0 + tx] = __float2bfloat16(tile[tx][ty + k * 8]);
    }
}

// ---------------------------------------------------------------------------
// P2: e -> bf16 + ||e||^2
// ---------------------------------------------------------------------------
__global__ void p_esplit(const float* __restrict__ e) {
    int w = (blockIdx.x * blockDim.x + threadIdx.x) >> 5;
    int lane = threadIdx.x & 31;
    if (w >= KC) return;
    const float* row = e + w * DIMV;
    float s = 0.f;
    #pragma unroll
    for (int i = 0; i < 8; i++) {
        int d = i * 32 + lane;
        float x = row[d];
        g_eh[w * DIMV + d] = __float2bfloat16(x);
        s += x * x;
    }
    #pragma unroll
    for (int o = 16; o; o >>= 1) s += __shfl_xor_sync(0xFFFFFFFFu, s, o);
    if (lane == 0) g_enorm[w] = s;
}

// ---------------------------------------------------------------------------
// K0: zero accumulators
// ---------------------------------------------------------------------------
__global__ void k_zero() {
    int i = blockIdx.x * blockDim.x + threadIdx.x;
    int stride = gridDim.x * blockDim.x;
    for (int j = i; j < KC * DIMV; j += stride) g_esum[j] = 0.f;
    for (int j = i; j < KC; j += stride) g_counts[j] = 0.f;
    if (i == 0) { g_loss = 0.0; g_nflag = 0; }
}

// ---------------------------------------------------------------------------
// K1: bf16 mma.sync GEMM (128 tokens x 8192 codes x 256) + candidate argmin.
// 256 threads = 8 warps, warp grid 4(M) x 2(N), warp tile 32x32, N-tile 64.
// s~ = ||e||^2 - 2 z.e (bf16). Running per-token min via smem atomicMin;
// codes with s~ < min + T appended; exact fp32 re-score of survivors at end.
// ---------------------------------------------------------------------------
__global__ void __launch_bounds__(256, 1)
k_dist_mma(const float* __restrict__ z, const float* __restrict__ e,
           float* __restrict__ out) {
    extern __shared__ char dsm[];
    uint32_t raw = smem_u32(dsm);
    uint32_t base = (raw + 1023u) & ~1023u;
    char* sm = dsm + (base - raw);

    int tid = threadIdx.x;
    int lane = tid & 31, wid = tid >> 5;
    int wm = wid & 3, wn = wid >> 2;
    int n0 = blockIdx.x * 128;

    int* cnt_sm = (int*)(sm + SCNT);
    uint32_t* mkey = (uint32_t*)(sm + SMK);
    int* scode = (int*)(sm + SCODE);
    float* ssv = (float*)(sm + SS);

    if (tid < 128) { cnt_sm[tid] = 0; mkey[tid] = 0xFFFFFFFFu; }

    // ---- prologue: A (g_zh rows) + B tiles 0,1 via cp.async (swizzled) ----
    #pragma unroll
    for (int i = 0; i < 16; i++) {
        int idx = tid + 256 * i;
        int row = idx >> 5, kc = idx & 31;
        uint32_t sa = base + SA + row * 512 + (((uint32_t)(kc << 4)) ^ ((row & 7) << 4));
        CP_ASYNC16(sa, (const void*)(g_zh + (size_t)(n0 + row) * DIMV + kc * 8));
    }
    {
        #pragma unroll
        for (int i = 0; i < 8; i++) {
            int idx = tid + 256 * i;
            int row = idx >> 5, kc = idx & 31;
            uint32_t sa = base + SB + row * 512 + (((uint32_t)(kc << 4)) ^ ((row & 7) << 4));
            CP_ASYNC16(sa, (const void*)(g_eh + (size_t)row * DIMV + kc * 8));
        }
    }
    CP_COMMIT();
    {
        #pragma unroll
        for (int i = 0; i < 8; i++) {
            int idx = tid + 256 * i;
            int row = idx >> 5, kc = idx & 31;
            uint32_t sa = base + SB + 32768 + row * 512 + (((uint32_t)(kc << 4)) ^ ((row & 7) << 4));
            CP_ASYNC16(sa, (const void*)(g_eh + (size_t)(NT + row) * DIMV + kc * 8));
        }
    }
    CP_COMMIT();

    // ldmatrix per-thread address pieces
    int grp = lane >> 3;
    int rA_off = (lane & 7) + ((grp & 1) << 3);      // row within m16
    uint32_t boA = (uint32_t)((grp >> 1) << 4);      // 0 or 16 bytes
    int rB_off = (lane & 7) + ((grp >> 1) << 3);     // row within n16
    uint32_t boB = (uint32_t)((grp & 1) << 4);

    // A frag row terms (mf = 0,1)
    uint32_t aRow[2], aSw[2];
    #pragma unroll
    for (int mf = 0; mf < 2; mf++) {
        int r = wm * 32 + mf * 16 + rA_off;
        aRow[mf] = base + SA + r * 512;
        aSw[mf] = (uint32_t)((r & 7) << 4);
    }
    // B frag row terms (pair = 0,1 -> n-blocks of 16)
    uint32_t bRow[2], bSw[2];
    #pragma unroll
    for (int p = 0; p < 2; p++) {
        int r = wn * 32 + p * 16 + rB_off;
        bRow[p] = r * 512;
        bSw[p] = (uint32_t)((r & 7) << 4);
    }

    float acc[32];

    for (int t = 0; t < TILES; t++) {
        CP_WAIT1();
        __syncthreads();

        #pragma unroll
        for (int i = 0; i < 32; i++) acc[i] = 0.f;

        uint32_t bbuf = base + SB + (uint32_t)(t & 1) * 32768u;

        #pragma unroll
        for (int ks = 0; ks < 16; ks++) {
            uint32_t kb = (uint32_t)(ks * 32);
            uint32_t a0[2], a1[2], a2[2], a3[2];
            #pragma unroll
            for (int mf = 0; mf < 2; mf++)
                ldsm4(a0[mf], a1[mf], a2[mf], a3[mf], aRow[mf] + ((kb + boA) ^ aSw[mf]));
            uint32_t b0[4], b1[4];
            #pragma unroll
            for (int p = 0; p < 2; p++) {
                uint32_t r0, r1, r2, r3;
                ldsm4(r0, r1, r2, r3, bbuf + bRow[p] + ((kb + boB) ^ bSw[p]));
                b0[p * 2] = r0; b1[p * 2] = r1; b0[p * 2 + 1] = r2; b1[p * 2 + 1] = r3;
            }
            #pragma unroll
            for (int mf = 0; mf < 2; mf++)
                #pragma unroll
                for (int nf = 0; nf < 4; nf++) {
                    int ix = mf * 16 + nf * 4;
                    mma16816(acc[ix], acc[ix + 1], acc[ix + 2], acc[ix + 3],
                             a0[mf], a1[mf], a2[mf], a3[mf], b0[nf], b1[nf]);
                }
        }

        __syncthreads();   // all reads of B buf (t&1) done

        if (t + 2 < TILES) {
            uint32_t db = base + SB + (uint32_t)(t & 1) * 32768u;
            const __nv_bfloat16* gsrc = g_eh + (size_t)(t + 2) * NT * DIMV;
            #pragma unroll
            for (int i = 0; i < 8; i++) {
                int idx = tid + 256 * i;
                int row = idx >> 5, kc = idx & 31;
                uint32_t sa = db + row * 512 + (((uint32_t)(kc << 4)) ^ ((row & 7) << 4));
                CP_ASYNC16(sa, (const void*)(gsrc + (size_t)row * DIMV + kc * 8));
            }
        }
        CP_COMMIT();

        // ---- epilogue pass 1: s~ in place + per-row mins + atomicMin ----
        float rmin[4] = {3.4e38f, 3.4e38f, 3.4e38f, 3.4e38f};
        #pragma unroll
        for (int nf = 0; nf < 4; nf++) {
            #pragma unroll
            for (int co = 0; co < 2; co++) {
                int code = t * NT + wn * 32 + nf * 8 + 2 * (lane & 3) + co;
                float en = __ldg(&g_enorm[code]);
                #pragma unroll
                for (int mf = 0; mf < 2; mf++) {
                    int ix = mf * 16 + nf * 4;
                    float v0 = fmaf(-2.f, acc[ix + co], en);
                    float v1 = fmaf(-2.f, acc[ix + 2 + co], en);
                    acc[ix + co] = v0; acc[ix + 2 + co] = v1;
                    rmin[mf * 2] = fminf(rmin[mf * 2], v0);
                    rmin[mf * 2 + 1] = fminf(rmin[mf * 2 + 1], v1);
                }
            }
        }
        #pragma unroll
        for (int mf = 0; mf < 2; mf++)
            #pragma unroll
            for (int h = 0; h < 2; h++) {
                int rowl = wm * 32 + mf * 16 + (lane >> 2) + h * 8;
                atomicMin(&mkey[rowl], fkey(rmin[mf * 2 + h]));
            }
        __syncthreads();   // tile-complete mins visible

        // ---- epilogue pass 2: append candidates ----
        #pragma unroll
        for (int mf = 0; mf < 2; mf++)
            #pragma unroll
            for (int h = 0; h < 2; h++) {
                int rowl = wm * 32 + mf * 16 + (lane >> 2) + h * 8;
                float th = funkey(mkey[rowl]) + TCAND;
                #pragma unroll
                for (int nf = 0; nf < 4; nf++)
                    #pragma unroll
                    for (int co = 0; co < 2; co++) {
                        float v = acc[mf * 16 + nf * 4 + h * 2 + co];
                        if (v < th) {
                            int code = t * NT + wn * 32 + nf * 8 + 2 * (lane & 3) + co;
                            int p = atomicAdd(&cnt_sm[rowl], 1);
                            if (p < 32) { scode[rowl * 32 + p] = code; ssv[rowl * 32 + p] = v; }
                        }
                    }
            }
    }

    __syncthreads();

    // ---- phase 3: exact fp32 re-score of surviving candidates ----
    if (tid < 128) {
        int token = n0 + tid;
        int c = cnt_sm[tid];
        if (c > 32) {
            int fi = atomicAdd(&g_nflag, 1);
            g_flaglist[fi] = token;
            c = 32;
        }
        float th = funkey(mkey[tid]) + TCAND;
        int b = token >> 10, hw = token & 1023;
        const float* zb = z + (size_t)b * BDHW + hw;
        float bestS = 3.4e38f; int bestC = 0x7fffffff;
        for (int i = 0; i < c; i++) {
            if (ssv[tid * 32 + i] <= th) {
                int code = scode[tid * 32 + i];
                const float* er = e + (size_t)code * DIMV;
                float dot = 0.f;
                #pragma unroll 8
                for (int d = 0; d < DIMV; d++) dot = fmaf(zb[d * HWSZ], er[d], dot);
                float s = __ldg(&g_enorm[code]) - 2.f * dot;
                if (s < bestS || (s == bestS && code < bestC)) { bestS = s; bestC = code; }
            }
        }
        g_idx[token] = bestC;
        out[IDX_OFF + token] = (float)bestC;
    }
}

// ---------------------------------------------------------------------------
// K1b: rescue — exact full scan for overflowed tokens (expected none)
// ---------------------------------------------------------------------------
__global__ void __launch_bounds__(256)
k_rescue(const float* __restrict__ z, const float* __restrict__ e,
         float* __restrict__ out) {
    __shared__ float zr[256];
    __shared__ unsigned long long red[256];
    int nf = g_nflag;
    for (int f = blockIdx.x; f < nf; f += gridDim.x) {
        int token = g_flaglist[f];
        int b = token >> 10, hw = token & 1023;
        zr[threadIdx.x] = z[(size_t)b * BDHW + threadIdx.x * HWSZ + hw];
        __syncthreads();
        unsigned long long best = 0xFFFFFFFFFFFFFFFFull;
        for (int c = threadIdx.x; c < KC; c += 256) {
            const float* er = e + (size_t)c * DIMV;
            float dot = 0.f;
            #pragma unroll 8
            for (int d = 0; d < DIMV; d++) dot = fmaf(zr[d], er[d], dot);
            float s = g_enorm[c] - 2.f * dot;
            unsigned long long p = ((unsigned long long)fkey(s) << 32) | (unsigned int)c;
            best = min(best, p);
        }
        red[threadIdx.x] = best;
        __syncthreads();
        for (int s = 128; s; s >>= 1) {
            if (threadIdx.x < s) red[threadIdx.x] = min(red[threadIdx.x], red[threadIdx.x + s]);
            __syncthreads();
        }
        if (threadIdx.x == 0) {
            int bc = (int)(red[0] & 0xFFFFFFFFu);
            g_idx[token] = bc;
            out[IDX_OFF + token] = (float)bc;
        }
        __syncthreads();
    }
}

// ---------------------------------------------------------------------------
// K2: gather/scatter. grid (token_block, d_chunk of 32)
// ---------------------------------------------------------------------------
__global__ void __launch_bounds__(128)
k_scatter(const float* __restrict__ z, const float* __restrict__ e,
          float* __restrict__ out) {
    int t = threadIdx.x;
    int n = blockIdx.x * 128 + t;
    int d0 = blockIdx.y * 32;
    int idx = g_idx[n];
    if (blockIdx.y == 0) atomicAdd(&g_counts[idx], 1.f);

    int b = n >> 10, hw = n & 1023;
    const float* zb = z + (size_t)b * BDHW + hw;
    float*       ob = out + OUT_OFF + (size_t)b * BDHW + hw;
    const float* er = e + (size_t)idx * DIMV;
    float* es = g_esum + (size_t)idx * DIMV;

    float lacc = 0.f;
    #pragma unroll
    for (int i = 0; i < 32; i++) {
        int d = d0 + i;
        float zv = zb[d * HWSZ];
        float diff = er[d] - zv;
        lacc += diff * diff;
        ob[d * HWSZ] = zv + diff;
        atomicAdd(&es[d], zv);
    }

    __shared__ float red[128];
    red[t] = lacc;
    __syncthreads();
    #pragma unroll
    for (int s = 64; s; s >>= 1) {
        if (t < s) red[t] += red[t + s];
        __syncthreads();
    }
    if (t == 0) atomicAdd(&g_loss, (double)red[0]);
}

// ---------------------------------------------------------------------------
// K3: cluster-size EMA + denom + loss finalize
// ---------------------------------------------------------------------------
__global__ void __launch_bounds__(1024)
k_cs(const float* __restrict__ cluster_size, float* __restrict__ out) {
    __shared__ float red[1024];
    int t = threadIdx.x;
    float csl[8];
    float local = 0.f;
    #pragma unroll
    for (int r = 0; r < 8; r++) {
        int k = t * 8 + r;
        float cs = cluster_size[k] * DECAYF + OMDF * g_counts[k] + EPSF;
        csl[r] = cs;
        local += cs;
    }
    red[t] = local;
    __syncthreads();
    #pragma unroll
    for (int s = 512; s; s >>= 1) {
        if (t < s) red[t] += red[t + s];
        __syncthreads();
    }
    float denom = red[0] + (float)(KC * 1e-05);
    #pragma unroll
    for (int r = 0; r < 8; r++) {
        int k = t * 8 + r;
        float v = csl[r] / denom;
        g_ncs[k] = v;
        out[CS_OFF + k] = v;
    }
    if (t == 0)
        out[LOSS_OFF] = (float)(0.25 * g_loss / (double)((size_t)NV * DIMV));
}

// ---------------------------------------------------------------------------
// K4: new_ema_w and new_embedding
// ---------------------------------------------------------------------------
__global__ void k_final(const float* __restrict__ ema_w, float* __restrict__ out) {
    int i = blockIdx.x * blockDim.x + threadIdx.x;
    if (i >= KC * DIMV) return;
    int k = i >> 8;
    float v = ema_w[i] * DECAYF + OMDF * g_esum[i];
    out[EMAW_OFF + i] = v;
    out[EMB_OFF + i]  = v / g_ncs[k];
}

// ---------------------------------------------------------------------------
extern "C" void kernel_launch(void* const* d_in, const int* in_sizes, int n_in,
                              void* d_out, int out_size) {
    (void)in_sizes; (void)n_in; (void)out_size;
    const float* z            = (const float*)d_in[0];
    const float* embedding    = (const float*)d_in[1];
    const float* cluster_size = (const float*)d_in[2];
    const float* ema_w        = (const float*)d_in[3];
    float* out = (float*)d_out;

    cudaFuncSetAttribute(k_dist_mma, cudaFuncAttributeMaxDynamicSharedMemorySize, SM_SZ);

    p_zsplit<<<dim3(32, 8, 16), dim3(32, 8)>>>(z);
    p_esplit<<<1024, 256>>>(embedding);
    k_zero<<<2048, 512>>>();
    k_dist_mma<<<128, 256, SM_SZ>>>(z, embedding, out);
    k_rescue<<<32, 256>>>(z, embedding, out);
    k_scatter<<<dim3(128, 8), 128>>>(z, embedding, out);
    k_cs<<<1, 1024>>>(cluster_size, out);
    k_final<<<8192, 256>>>(ema_w, out);
}